// round 2
// baseline (speedup 1.0000x reference)
#include <cuda_runtime.h>
#include <cuda_bf16.h>
#include <cstdint>

// Clipped Poisson-binomial severity kernel, round 2.
// Persistent blocks, double-buffered cp.async pipeline, packed f32x2 recurrence
// (2 rows per thread) so the fma pipe can never pace the HBM stream.

#define NT 128               // threads per block (4 warps -> one per SMSP)
#define TROWS 256            // rows per tile (2 per thread)
#define SSTRIDE 36           // padded floats per smem row (conflict-free LDS.128)
#define TILE_FLOATS (3 * TROWS * SSTRIDE)          // 27,648 floats = 110,592 B
#define SMEM_BYTES (2 * TILE_FLOATS * 4)           // 221,184 B (double buffer)

typedef unsigned long long u64;

__device__ __forceinline__ u64 pk2(float a, float b) {
    u64 r; asm("mov.b64 %0, {%1, %2};" : "=l"(r) : "f"(a), "f"(b)); return r;
}
__device__ __forceinline__ void upk2(u64 v, float& a, float& b) {
    asm("mov.b64 {%0, %1}, %2;" : "=f"(a), "=f"(b) : "l"(v));
}
__device__ __forceinline__ u64 fma2(u64 a, u64 b, u64 c) {
    u64 d; asm("fma.rn.f32x2 %0, %1, %2, %3;" : "=l"(d) : "l"(a), "l"(b), "l"(c)); return d;
}

__global__ void __launch_bounds__(NT, 1)
hemorrhage_sev_kernel(const float* __restrict__ x1,
                      const float* __restrict__ x2,
                      const float* __restrict__ x3,
                      float* __restrict__ out,
                      int ntiles, int nrows)
{
    extern __shared__ float smem[];
    float* bufs[2] = { smem, smem + TILE_FLOATS };

    const int t = threadIdx.x;
    const float* srcs[3] = { x1, x2, x3 };

    // ---- staging helper: coalesced cp.async of one 3x(256x32) fp32 tile ----
    auto stage = [&](float* buf, int tile) {
        const long long rowBase = (long long)tile * TROWS;
        #pragma unroll
        for (int in = 0; in < 3; ++in) {
            const float4* gp = (const float4*)(srcs[in] + rowBase * 32);
            float* bb = buf + in * (TROWS * SSTRIDE);
            #pragma unroll
            for (int k = 0; k < 16; ++k) {           // 16*128 = 2048 float4 / input
                int i = k * NT + t;
                int row = i >> 3;                    // 8 float4 per row
                int col4 = i & 7;
                float* dst = bb + row * SSTRIDE + col4 * 4;
                unsigned saddr = (unsigned)__cvta_generic_to_shared(dst);
                int srcsz = (rowBase + row < (long long)nrows) ? 16 : 0;  // zfill OOB
                asm volatile("cp.async.cg.shared.global [%0], [%1], 16, %2;\n"
                             :: "r"(saddr), "l"(gp + i), "r"(srcsz));
            }
        }
        asm volatile("cp.async.commit_group;\n");
    };

    int tile = blockIdx.x;
    const int step = gridDim.x;
    if (tile < ntiles) stage(bufs[0], tile);

    int parity = 0;
    for (; tile < ntiles; tile += step) {
        const int next = tile + step;
        const bool hasNext = (next < ntiles);
        if (hasNext) stage(bufs[parity ^ 1], next);

        if (hasNext) asm volatile("cp.async.wait_group 1;\n");
        else         asm volatile("cp.async.wait_group 0;\n");
        __syncthreads();

        const float* cur = bufs[parity];

        // ---- packed recurrence: thread owns rows (t) and (t+128) of tile ----
        u64 c0 = pk2(1.f, 1.f), c1 = 0, c2 = 0, c3 = 0, c4 = 0, c5 = 0;
        for (int in = 0; in < 3; ++in) {
            const float* rA = cur + in * (TROWS * SSTRIDE) + t * SSTRIDE;
            const float* rB = rA + 128 * SSTRIDE;
            #pragma unroll
            for (int j4 = 0; j4 < 8; ++j4) {
                float4 va = *(const float4*)(rA + j4 * 4);
                float4 vb = *(const float4*)(rB + j4 * 4);
                float pa[4] = { va.x, va.y, va.z, va.w };
                float pb[4] = { vb.x, vb.y, vb.z, vb.w };
                #pragma unroll
                for (int u = 0; u < 4; ++u) {
                    u64 p  = pk2(pa[u], pb[u]);
                    u64 np = p ^ 0x8000000080000000ull;       // -p (alu pipe)
                    c5 = fma2(c4, p, c5);                     // uses old c4
                    c4 = fma2(c3, p, fma2(c4, np, c4));       // c4(1-p)+c3*p
                    c3 = fma2(c2, p, fma2(c3, np, c3));
                    c2 = fma2(c1, p, fma2(c2, np, c2));
                    c1 = fma2(c0, p, fma2(c1, np, c1));
                    c0 = fma2(c0, np, c0);                    // c0 *= (1-p)
                }
            }
        }
        __syncthreads();   // all lanes done reading this buffer before refill

        // ---- write outputs: 5 floats per row ----
        const long long rowBase = (long long)tile * TROWS;
        float a0,b0,a1,b1,a2,b2,a3,b3,a4,b4,a5,b5;
        upk2(c0,a0,b0); upk2(c1,a1,b1); upk2(c2,a2,b2);
        upk2(c3,a3,b3); upk2(c4,a4,b4); upk2(c5,a5,b5);

        long long rAi = rowBase + t;
        long long rBi = rowBase + t + 128;
        if (rAi < nrows) {
            float* o = out + rAi * 5;
            o[0] = a0; o[1] = a1 + a2; o[2] = a3 + a4; o[3] = a5; o[4] = 0.f;
        }
        if (rBi < nrows) {
            float* o = out + rBi * 5;
            o[0] = b0; o[1] = b1 + b2; o[2] = b3 + b4; o[3] = b5; o[4] = 0.f;
        }

        parity ^= 1;
    }
}

extern "C" void kernel_launch(void* const* d_in, const int* in_sizes, int n_in,
                              void* d_out, int out_size)
{
    const float* x1 = (const float*)d_in[0];
    const float* x2 = (const float*)d_in[1];
    const float* x3 = (const float*)d_in[2];
    float* out = (float*)d_out;

    const int nrows = in_sizes[0] / 32;
    const int ntiles = (nrows + TROWS - 1) / TROWS;

    int dev = 0, nsm = 148;
    cudaGetDevice(&dev);
    cudaDeviceGetAttribute(&nsm, cudaDevAttrMultiProcessorCount, dev);

    static bool attrSet = false;
    if (!attrSet) {
        cudaFuncSetAttribute(hemorrhage_sev_kernel,
                             cudaFuncAttributeMaxDynamicSharedMemorySize, SMEM_BYTES);
        attrSet = true;
    }

    int grid = ntiles < nsm ? ntiles : nsm;
    hemorrhage_sev_kernel<<<grid, NT, SMEM_BYTES>>>(x1, x2, x3, out, ntiles, nrows);
}

// round 3
// speedup vs baseline: 1.5141x; 1.5141x over previous
#include <cuda_runtime.h>
#include <cuda_bf16.h>
#include <cstdint>

// Clipped Poisson-binomial severity kernel, round 3.
// Back to R1's many-independent-blocks structure (that's what fed DRAM at 79.5%),
// plus: per-input cp.async commit groups with progressive waits (compute on x1
// starts while x2/x3 are still in flight), and 128-row blocks (4 blocks/SM,
// 16 warps/SM) to halve launch overhead at identical SM-level concurrency.

#define NT 128               // threads per block
#define ROWS 128             // rows per block (1 per thread)
#define SSTRIDE 36           // padded floats per smem row -> conflict-free LDS.128
#define IN_FLOATS (ROWS * SSTRIDE)   // 4608 floats per input tile

__global__ __launch_bounds__(NT)
void hemorrhage_sev_kernel(const float* __restrict__ x1,
                           const float* __restrict__ x2,
                           const float* __restrict__ x3,
                           float* __restrict__ out,
                           int nrows)
{
    __shared__ float s[3 * IN_FLOATS];          // 55,296 B -> 4 blocks/SM
    __shared__ float so[ROWS * 5];              // 2,560 B output staging

    const int t = threadIdx.x;
    const long long rowBase = (long long)blockIdx.x * ROWS;
    const int rowsHere = (int)min((long long)ROWS, (long long)nrows - rowBase);

    const float* srcs[3] = { x1 + rowBase * 32, x2 + rowBase * 32, x3 + rowBase * 32 };

    // ---- Stage all three inputs, one commit group per input ----
    #pragma unroll
    for (int in = 0; in < 3; ++in) {
        const float4* gp = (const float4*)srcs[in];
        float* bb = s + in * IN_FLOATS;
        #pragma unroll
        for (int k = 0; k < 8; ++k) {            // 8 * 128 = 1024 float4 per input
            int i = k * NT + t;
            int row  = i >> 3;                   // 8 float4 per row
            int col4 = i & 7;
            float* dst = bb + row * SSTRIDE + col4 * 4;
            unsigned saddr = (unsigned)__cvta_generic_to_shared(dst);
            int srcsz = (row < rowsHere) ? 16 : 0;   // zero-fill OOB rows
            asm volatile("cp.async.cg.shared.global [%0], [%1], 16, %2;\n"
                         :: "r"(saddr), "l"(gp + i), "r"(srcsz));
        }
        asm volatile("cp.async.commit_group;\n");
    }

    // ---- Recurrence, consuming inputs as their groups land ----
    float c0 = 1.f, c1 = 0.f, c2 = 0.f, c3 = 0.f, c4 = 0.f, c5 = 0.f;

    #pragma unroll
    for (int in = 0; in < 3; ++in) {
        if (in == 0)      asm volatile("cp.async.wait_group 2;\n");
        else if (in == 1) asm volatile("cp.async.wait_group 1;\n");
        else              asm volatile("cp.async.wait_group 0;\n");
        __syncthreads();   // group completion is per-thread; make tile visible block-wide

        const float* rowp = s + in * IN_FLOATS + t * SSTRIDE;
        #pragma unroll
        for (int j4 = 0; j4 < 8; ++j4) {
            float4 v = *(const float4*)(rowp + j4 * 4);
            float pv[4] = { v.x, v.y, v.z, v.w };
            #pragma unroll
            for (int u = 0; u < 4; ++u) {
                float p = pv[u];
                c5 = fmaf(c4, p, c5);            // absorbing top bucket
                c4 = fmaf(c3 - c4, p, c4);
                c3 = fmaf(c2 - c3, p, c3);
                c2 = fmaf(c1 - c2, p, c2);
                c1 = fmaf(c0 - c1, p, c1);
                c0 = fmaf(-c0, p, c0);           // c0 *= (1-p)
            }
        }
    }

    // ---- Stage output (stride-5 STS, gcd(5,32)=1 -> conflict-free), then
    //      fully coalesced 4B stores ----
    so[t * 5 + 0] = c0;
    so[t * 5 + 1] = c1 + c2;
    so[t * 5 + 2] = c3 + c4;
    so[t * 5 + 3] = c5;
    so[t * 5 + 4] = 0.f;
    __syncthreads();

    float* og = out + rowBase * 5;
    const int nOut = rowsHere * 5;
    #pragma unroll
    for (int k = 0; k < 5; ++k) {
        int idx = k * NT + t;
        if (idx < nOut) og[idx] = so[idx];
    }
}

extern "C" void kernel_launch(void* const* d_in, const int* in_sizes, int n_in,
                              void* d_out, int out_size)
{
    const float* x1 = (const float*)d_in[0];
    const float* x2 = (const float*)d_in[1];
    const float* x3 = (const float*)d_in[2];
    float* out = (float*)d_out;

    const int nrows = in_sizes[0] / 32;
    const int nblocks = (nrows + ROWS - 1) / ROWS;

    hemorrhage_sev_kernel<<<nblocks, NT>>>(x1, x2, x3, out, nrows);
}